// round 2
// baseline (speedup 1.0000x reference)
#include <cuda_runtime.h>

// Problem constants
#define NB 16      // batch
#define NG 64      // groups (N)
#define NS 4096    // key sequence
#define NC 384     // channels
#define NH 6       // heads
#define ND 64      // head dim

// GEMM tile config: 128x64 block tile, 16 k-slice, 256 threads, 8x4 per thread
#define BM 128
#define BN 64
#define BK 16
#define AP 132     // As pitch (padded)
#define BP2 68     // Bs pitch (padded)

// Scratch (device globals — no runtime allocation allowed)
__device__ float g_qT[NB * NH * ND * NG];   // q transposed: [b][h][d][n]
__device__ int   g_idx[NB * NH * NS];       // argmax group per key token
__device__ float g_acc[NB * NH * NG * ND];  // per-group v accumulator
__device__ int   g_cnt[NB * NH * NG];       // per-group counts

// ---------------------------------------------------------------------------
// Shared GEMM helpers: C[m,n] = sum_k A[m,k] * W[n,k]  (A,W row-major, lda=384)
// ---------------------------------------------------------------------------
__device__ __forceinline__ void load_A_tile(const float* __restrict__ A,
                                            int mBase, int k0, float* As, int tid) {
#pragma unroll
    for (int l = 0; l < 2; ++l) {
        int lin = tid * 2 + l;           // 0..511
        int m = lin >> 2;                // 0..127
        int kg = (lin & 3) * 4;          // 0,4,8,12
        float4 v = *(const float4*)(A + (size_t)(mBase + m) * NC + k0 + kg);
        As[(kg + 0) * AP + m] = v.x;
        As[(kg + 1) * AP + m] = v.y;
        As[(kg + 2) * AP + m] = v.z;
        As[(kg + 3) * AP + m] = v.w;
    }
}

__device__ __forceinline__ void load_B_tile(const float* __restrict__ W,
                                            int nBase, int k0, float* Bs, int tid) {
    int wr = tid >> 2;                   // 0..63
    int kg = (tid & 3) * 4;              // 0,4,8,12
    float4 v = *(const float4*)(W + (size_t)(nBase + wr) * NC + k0 + kg);
    Bs[(kg + 0) * BP2 + wr] = v.x;
    Bs[(kg + 1) * BP2 + wr] = v.y;
    Bs[(kg + 2) * BP2 + wr] = v.z;
    Bs[(kg + 3) * BP2 + wr] = v.w;
}

__device__ __forceinline__ void mma_tile(const float* As, const float* Bs,
                                         float c[8][4], int trow, int tcol) {
#pragma unroll
    for (int k = 0; k < BK; ++k) {
        float4 a0 = *(const float4*)(As + k * AP + trow * 8);
        float4 a1 = *(const float4*)(As + k * AP + trow * 8 + 4);
        float4 b0 = *(const float4*)(Bs + k * BP2 + tcol * 4);
        float a[8] = {a0.x, a0.y, a0.z, a0.w, a1.x, a1.y, a1.z, a1.w};
        float b[4] = {b0.x, b0.y, b0.z, b0.w};
#pragma unroll
        for (int i = 0; i < 8; ++i)
#pragma unroll
            for (int j = 0; j < 4; ++j)
                c[i][j] += a[i] * b[j];
    }
}

// ---------------------------------------------------------------------------
// K0: zero accumulators (must run every launch — graph replays)
// ---------------------------------------------------------------------------
__global__ void k_zero() {
    int i = blockIdx.x * blockDim.x + threadIdx.x;
    if (i < NB * NH * NG * ND) g_acc[i] = 0.0f;
    if (i < NB * NH * NG) g_cnt[i] = 0;
}

// ---------------------------------------------------------------------------
// K1: q projection -> g_qT[b][h][d][n]
// grid (8, 6): 8 M-blocks of 128 rows (M = B*N = 1024), 6 head column blocks
// ---------------------------------------------------------------------------
__global__ void __launch_bounds__(256) k_qproj(const float* __restrict__ query,
                                               const float* __restrict__ Wq) {
    __shared__ float As[BK * AP];
    __shared__ float Bs[BK * BP2];
    int tid = threadIdx.x;
    int trow = tid >> 4, tcol = tid & 15;
    int mBase = blockIdx.x * BM;
    int h = blockIdx.y;
    int nBase = h * 64;

    float c[8][4] = {};
    for (int k0 = 0; k0 < NC; k0 += BK) {
        load_A_tile(query, mBase, k0, As, tid);
        load_B_tile(Wq, nBase, k0, Bs, tid);
        __syncthreads();
        mma_tile(As, Bs, c, trow, tcol);
        __syncthreads();
    }
#pragma unroll
    for (int i = 0; i < 8; ++i) {
        int m = mBase + trow * 8 + i;
        int b = m >> 6, n = m & 63;
#pragma unroll
        for (int j = 0; j < 4; ++j) {
            int d = tcol * 4 + j;
            g_qT[((b * NH + h) * ND + d) * NG + n] = c[i][j];
        }
    }
}

// ---------------------------------------------------------------------------
// K2: kp = key@Wk^T (never stored), fused scores vs q + argmax -> g_idx, g_cnt
// grid (512, 6): 512 row tiles of 128 key tokens, 6 heads
// ---------------------------------------------------------------------------
__global__ void __launch_bounds__(256) k_kproj_assign(const float* __restrict__ key,
                                                      const float* __restrict__ Wk) {
    __shared__ union SmemU {
        struct { float As[BK * AP]; float Bs[BK * BP2]; } g;
        struct { float Kp[64 * 64]; float Qs[64 * 64]; } e;  // 32 KB
    } sm;

    int tid = threadIdx.x;
    int trow = tid >> 4, tcol = tid & 15;
    int mBase = blockIdx.x * BM;            // global row in [0, B*S)
    int b = mBase >> 12;                    // / 4096
    int sBase = mBase & (NS - 1);
    int h = blockIdx.y;
    int nBase = h * 64;
    int bh = b * NH + h;

    float c[8][4] = {};
    for (int k0 = 0; k0 < NC; k0 += BK) {
        load_A_tile(key, mBase, k0, sm.g.As, tid);
        load_B_tile(Wk, nBase, k0, sm.g.Bs, tid);
        __syncthreads();
        mma_tile(sm.g.As, sm.g.Bs, c, trow, tcol);
        __syncthreads();
    }

    // Load q[b,h] ([d][n] layout) into smem (doesn't alias As/Bs footprint issue
    // after the sync above; Qs region sits above As+Bs anyway)
    const float* qsrc = g_qT + (size_t)bh * ND * NG;
#pragma unroll
    for (int r = 0; r < 4; ++r) {
        int off = (tid + 256 * r) * 4;
        *(float4*)&sm.e.Qs[off] = *(const float4*)&qsrc[off];
    }

    // Epilogue in two halves of 64 key rows to keep smem at 32 KB
#pragma unroll
    for (int hlf = 0; hlf < 2; ++hlf) {
        __syncthreads();  // previous half's reads done / Qs visible
        if ((trow >> 3) == hlf) {
#pragma unroll
            for (int i = 0; i < 8; ++i) {
                int lrow = (trow & 7) * 8 + i;
                *(float4*)&sm.e.Kp[lrow * 64 + tcol * 4] =
                    make_float4(c[i][0], c[i][1], c[i][2], c[i][3]);
            }
        }
        __syncthreads();

        // scores[64 s][64 n] = Kp @ Qs^T : each thread 4x4 sub-tile
        int trow2 = tid >> 4;
        float acc2[4][4] = {};
#pragma unroll 16
        for (int d = 0; d < 64; ++d) {
            float a[4];
#pragma unroll
            for (int i2 = 0; i2 < 4; ++i2)
                a[i2] = sm.e.Kp[(trow2 * 4 + i2) * 64 + d];
            float4 q4 = *(const float4*)&sm.e.Qs[d * 64 + tcol * 4];
#pragma unroll
            for (int i2 = 0; i2 < 4; ++i2) {
                acc2[i2][0] += a[i2] * q4.x;
                acc2[i2][1] += a[i2] * q4.y;
                acc2[i2][2] += a[i2] * q4.z;
                acc2[i2][3] += a[i2] * q4.w;
            }
        }

        // argmax over n (64) per s row; 16 lanes per row -> shuffle reduce
#pragma unroll
        for (int i2 = 0; i2 < 4; ++i2) {
            float mv = acc2[i2][0];
            int mi = tcol * 4;
#pragma unroll
            for (int j = 1; j < 4; ++j) {
                if (acc2[i2][j] > mv) { mv = acc2[i2][j]; mi = tcol * 4 + j; }
            }
#pragma unroll
            for (int off = 8; off >= 1; off >>= 1) {
                float ov = __shfl_down_sync(0xffffffffu, mv, off, 16);
                int   oi = __shfl_down_sync(0xffffffffu, mi, off, 16);
                if (ov > mv || (ov == mv && oi < mi)) { mv = ov; mi = oi; }
            }
            if (tcol == 0) {
                int s = sBase + hlf * 64 + trow2 * 4 + i2;
                g_idx[bh * NS + s] = mi;
                atomicAdd(&g_cnt[bh * NG + mi], 1);
            }
        }
    }
}

// ---------------------------------------------------------------------------
// K3: vp = key@Wv^T (never stored), fused scatter into g_acc via g_idx
// grid (512, 6)
// ---------------------------------------------------------------------------
__global__ void __launch_bounds__(256) k_vproj_scatter(const float* __restrict__ key,
                                                       const float* __restrict__ Wv) {
    __shared__ float As[BK * AP];
    __shared__ float Bs[BK * BP2];
    int tid = threadIdx.x;
    int trow = tid >> 4, tcol = tid & 15;
    int mBase = blockIdx.x * BM;
    int b = mBase >> 12;
    int sBase = mBase & (NS - 1);
    int h = blockIdx.y;
    int nBase = h * 64;
    int bh = b * NH + h;

    float c[8][4] = {};
    for (int k0 = 0; k0 < NC; k0 += BK) {
        load_A_tile(key, mBase, k0, As, tid);
        load_B_tile(Wv, nBase, k0, Bs, tid);
        __syncthreads();
        mma_tile(As, Bs, c, trow, tcol);
        __syncthreads();
    }

#pragma unroll
    for (int i = 0; i < 8; ++i) {
        int s = sBase + trow * 8 + i;
        int n = g_idx[bh * NS + s];
        float* dst = &g_acc[(bh * NG + n) * ND + tcol * 4];
#pragma unroll
        for (int j = 0; j < 4; ++j) atomicAdd(dst + j, c[i][j]);
    }
}

// ---------------------------------------------------------------------------
// K4: tmp[b,n,c] = g_acc[b, c/64, n, c%64] / (cnt+1);  out = tmp @ Wp^T + bp
// grid (8, 6)
// ---------------------------------------------------------------------------
__global__ void __launch_bounds__(256) k_finalize(const float* __restrict__ Wp,
                                                  const float* __restrict__ bp,
                                                  float* __restrict__ out) {
    __shared__ float As[BK * AP];
    __shared__ float Bs[BK * BP2];
    int tid = threadIdx.x;
    int trow = tid >> 4, tcol = tid & 15;
    int mBase = blockIdx.x * BM;
    int nBase = blockIdx.y * BN;

    float c[8][4] = {};
    for (int k0 = 0; k0 < NC; k0 += BK) {
        // Custom A loader: normalized group accumulators
#pragma unroll
        for (int l = 0; l < 2; ++l) {
            int lin = tid * 2 + l;
            int m = lin >> 2;
            int kg = (lin & 3) * 4;
            int gm = mBase + m;
            int b = gm >> 6, n = gm & 63;
            int cc = k0 + kg;
            int h = cc >> 6, d = cc & 63;
            int bh = b * NH + h;
            float inv = 1.0f / (float)(g_cnt[bh * NG + n] + 1);
            float4 v = *(const float4*)&g_acc[(bh * NG + n) * ND + d];
            As[(kg + 0) * AP + m] = v.x * inv;
            As[(kg + 1) * AP + m] = v.y * inv;
            As[(kg + 2) * AP + m] = v.z * inv;
            As[(kg + 3) * AP + m] = v.w * inv;
        }
        load_B_tile(Wp, nBase, k0, Bs, tid);
        __syncthreads();
        mma_tile(As, Bs, c, trow, tcol);
        __syncthreads();
    }

    float4 bias = *(const float4*)&bp[nBase + tcol * 4];
#pragma unroll
    for (int i = 0; i < 8; ++i) {
        int m = mBase + trow * 8 + i;
        float4 v = make_float4(c[i][0] + bias.x, c[i][1] + bias.y,
                               c[i][2] + bias.z, c[i][3] + bias.w);
        *(float4*)&out[(size_t)m * NC + nBase + tcol * 4] = v;
    }
}

// ---------------------------------------------------------------------------
extern "C" void kernel_launch(void* const* d_in, const int* in_sizes, int n_in,
                              void* d_out, int out_size) {
    const float* query = (const float*)d_in[0];
    const float* key   = (const float*)d_in[1];
    const float* Wq    = (const float*)d_in[2];
    const float* Wk    = (const float*)d_in[3];
    const float* Wv    = (const float*)d_in[4];
    const float* Wp    = (const float*)d_in[5];
    const float* bp    = (const float*)d_in[6];
    float* out = (float*)d_out;

    k_zero<<<(NB * NH * NG * ND + 255) / 256, 256>>>();
    k_qproj<<<dim3(8, 6), 256>>>(query, Wq);
    k_kproj_assign<<<dim3((NB * NS) / BM, NH), 256>>>(key, Wk);
    k_vproj_scatter<<<dim3((NB * NS) / BM, NH), 256>>>(key, Wv);
    k_finalize<<<dim3(8, 6), 256>>>(Wp, bp, out);
}

// round 3
// speedup vs baseline: 2.4765x; 2.4765x over previous
#include <cuda_runtime.h>
#include <cstdint>

// Problem constants
#define NB 16
#define NG 64
#define NS 4096
#define NC 384
#define NH 6
#define ND 64

// fp32 helper-GEMM tile config (K1/K4, small)
#define BM 128
#define BN 64
#define BK 16
#define AP 132
#define BP2 68

// tf32 GEMM smem pitch (conflict-free fragment loads)
#define PA 20

// Scratch
__device__ __align__(16) float g_qT[NB * NH * ND * NG];   // q^T: [b][h][d][n]
__device__ int   g_idx[NB * NH * NS];
__device__ __align__(16) float g_acc[NB * NH * NG * ND];
__device__ int   g_cnt[NB * NH * NG];

// ---------------------------------------------------------------------------
// tf32 helpers
// ---------------------------------------------------------------------------
__device__ __forceinline__ uint32_t f2tf(float x) {
    uint32_t u;
    asm("cvt.rna.tf32.f32 %0, %1;" : "=r"(u) : "f"(x));
    return u;
}

__device__ __forceinline__ void mma_tf32(float c[4], const uint32_t a[4],
                                         const uint32_t b[2]) {
    asm volatile(
        "mma.sync.aligned.m16n8k8.row.col.f32.tf32.tf32.f32 "
        "{%0,%1,%2,%3}, {%4,%5,%6,%7}, {%8,%9}, {%0,%1,%2,%3};"
        : "+f"(c[0]), "+f"(c[1]), "+f"(c[2]), "+f"(c[3])
        : "r"(a[0]), "r"(a[1]), "r"(a[2]), "r"(a[3]), "r"(b[0]), "r"(b[1]));
}

template <bool SPLIT>
__device__ __forceinline__ void sts_split(float* hi, float* lo, int off, float4 v) {
    float x[4] = {v.x, v.y, v.z, v.w};
#pragma unroll
    for (int j = 0; j < 4; ++j) {
        uint32_t h = f2tf(x[j]);
        hi[off + j] = __uint_as_float(h);
        if (SPLIT)
            lo[off + j] = __uint_as_float(f2tf(x[j] - __uint_as_float(h)));
    }
}

// 128x64 block tile, K=384, 256 threads (8 warps: warpM in 0..3 x warpN in 0..1,
// warp tile 32x32). C[m][n] = sum_k A[mBase+m][k] * W[n][k].
// SPLIT=true: 3xTF32 (fp32-accurate). SPLIT=false: 1xTF32.
template <bool SPLIT>
__device__ __forceinline__ void gemm_tf32_128x64(
    const float* __restrict__ A, const float* __restrict__ W, int mBase,
    float c[2][4][4], float* sAh, float* sAl, float* sBh, float* sBl, int tid) {
    int lane = tid & 31;
    int warpM = (tid >> 5) & 3;
    int warpN = tid >> 7;
    int grp = lane >> 2, qd = lane & 3;

    int am0 = tid >> 2;            // 0..63
    int ak = (tid & 3) * 4;
    const float* pa0 = A + (size_t)(mBase + am0) * NC + ak;
    const float* pa1 = A + (size_t)(mBase + am0 + 64) * NC + ak;
    const float* pb  = W + (size_t)am0 * NC + ak;

    float4 ra0 = *(const float4*)pa0;
    float4 ra1 = *(const float4*)pa1;
    float4 rb  = *(const float4*)pb;

    for (int kt = 0; kt < NC / 16; ++kt) {
        __syncthreads();
        sts_split<SPLIT>(sAh, sAl, am0 * PA + ak, ra0);
        sts_split<SPLIT>(sAh, sAl, (am0 + 64) * PA + ak, ra1);
        sts_split<SPLIT>(sBh, sBl, am0 * PA + ak, rb);
        __syncthreads();
        if (kt < NC / 16 - 1) {
            int k0 = (kt + 1) * 16;
            ra0 = *(const float4*)(pa0 + k0);
            ra1 = *(const float4*)(pa1 + k0);
            rb  = *(const float4*)(pb + k0);
        }
#pragma unroll
        for (int kk = 0; kk < 16; kk += 8) {
            uint32_t ah[2][4], al[2][4], bh[4][2], bl[4][2];
#pragma unroll
            for (int mi = 0; mi < 2; ++mi) {
                int r = warpM * 32 + mi * 16 + grp;
                const float* bse = sAh + r * PA + kk + qd;
                ah[mi][0] = __float_as_uint(bse[0]);
                ah[mi][1] = __float_as_uint(bse[8 * PA]);
                ah[mi][2] = __float_as_uint(bse[4]);
                ah[mi][3] = __float_as_uint(bse[8 * PA + 4]);
                if (SPLIT) {
                    const float* bsl = sAl + r * PA + kk + qd;
                    al[mi][0] = __float_as_uint(bsl[0]);
                    al[mi][1] = __float_as_uint(bsl[8 * PA]);
                    al[mi][2] = __float_as_uint(bsl[4]);
                    al[mi][3] = __float_as_uint(bsl[8 * PA + 4]);
                }
            }
#pragma unroll
            for (int nj = 0; nj < 4; ++nj) {
                int cn = warpN * 32 + nj * 8 + grp;
                const float* bse = sBh + cn * PA + kk + qd;
                bh[nj][0] = __float_as_uint(bse[0]);
                bh[nj][1] = __float_as_uint(bse[4]);
                if (SPLIT) {
                    const float* bsl = sBl + cn * PA + kk + qd;
                    bl[nj][0] = __float_as_uint(bsl[0]);
                    bl[nj][1] = __float_as_uint(bsl[4]);
                }
            }
#pragma unroll
            for (int mi = 0; mi < 2; ++mi)
#pragma unroll
                for (int nj = 0; nj < 4; ++nj) {
                    if (SPLIT) {
                        mma_tf32(c[mi][nj], al[mi], bh[nj]);
                        mma_tf32(c[mi][nj], ah[mi], bl[nj]);
                    }
                    mma_tf32(c[mi][nj], ah[mi], bh[nj]);
                }
        }
    }
}

// ---------------------------------------------------------------------------
// fp32 helper GEMM pieces (K1 / K4 — small)
// ---------------------------------------------------------------------------
__device__ __forceinline__ void load_A_tile(const float* __restrict__ A,
                                            int mBase, int k0, float* As, int tid) {
#pragma unroll
    for (int l = 0; l < 2; ++l) {
        int lin = tid * 2 + l;
        int m = lin >> 2;
        int kg = (lin & 3) * 4;
        float4 v = *(const float4*)(A + (size_t)(mBase + m) * NC + k0 + kg);
        As[(kg + 0) * AP + m] = v.x;
        As[(kg + 1) * AP + m] = v.y;
        As[(kg + 2) * AP + m] = v.z;
        As[(kg + 3) * AP + m] = v.w;
    }
}

__device__ __forceinline__ void load_B_tile(const float* __restrict__ W,
                                            int nBase, int k0, float* Bs, int tid) {
    int wr = tid >> 2;
    int kg = (tid & 3) * 4;
    float4 v = *(const float4*)(W + (size_t)(nBase + wr) * NC + k0 + kg);
    Bs[(kg + 0) * BP2 + wr] = v.x;
    Bs[(kg + 1) * BP2 + wr] = v.y;
    Bs[(kg + 2) * BP2 + wr] = v.z;
    Bs[(kg + 3) * BP2 + wr] = v.w;
}

__device__ __forceinline__ void mma_tile(const float* As, const float* Bs,
                                         float c[8][4], int trow, int tcol) {
#pragma unroll
    for (int k = 0; k < BK; ++k) {
        float4 a0 = *(const float4*)(As + k * AP + trow * 8);
        float4 a1 = *(const float4*)(As + k * AP + trow * 8 + 4);
        float4 b0 = *(const float4*)(Bs + k * BP2 + tcol * 4);
        float a[8] = {a0.x, a0.y, a0.z, a0.w, a1.x, a1.y, a1.z, a1.w};
        float b[4] = {b0.x, b0.y, b0.z, b0.w};
#pragma unroll
        for (int i = 0; i < 8; ++i)
#pragma unroll
            for (int j = 0; j < 4; ++j)
                c[i][j] += a[i] * b[j];
    }
}

// ---------------------------------------------------------------------------
// K0: zero accumulators
// ---------------------------------------------------------------------------
__global__ void k_zero() {
    int i = blockIdx.x * blockDim.x + threadIdx.x;
    if (i < NB * NH * NG * ND) g_acc[i] = 0.0f;
    if (i < NB * NH * NG) g_cnt[i] = 0;
}

// ---------------------------------------------------------------------------
// K1: q projection -> g_qT[b][h][d][n] (fp32, tiny)
// ---------------------------------------------------------------------------
__global__ void __launch_bounds__(256) k_qproj(const float* __restrict__ query,
                                               const float* __restrict__ Wq) {
    __shared__ float As[BK * AP];
    __shared__ float Bs[BK * BP2];
    int tid = threadIdx.x;
    int trow = tid >> 4, tcol = tid & 15;
    int mBase = blockIdx.x * BM;
    int h = blockIdx.y;

    float c[8][4] = {};
    for (int k0 = 0; k0 < NC; k0 += BK) {
        load_A_tile(query, mBase, k0, As, tid);
        load_B_tile(Wq, h * 64, k0, Bs, tid);
        __syncthreads();
        mma_tile(As, Bs, c, trow, tcol);
        __syncthreads();
    }
#pragma unroll
    for (int i = 0; i < 8; ++i) {
        int m = mBase + trow * 8 + i;
        int b = m >> 6, n = m & 63;
#pragma unroll
        for (int j = 0; j < 4; ++j) {
            int d = tcol * 4 + j;
            g_qT[((b * NH + h) * ND + d) * NG + n] = c[i][j];
        }
    }
}

// ---------------------------------------------------------------------------
// K2: kp = key@Wk^T via 3xTF32 (fp32-accurate) + fused score/argmax epilogue
// ---------------------------------------------------------------------------
__global__ void __launch_bounds__(256) k2_assign(const float* __restrict__ key,
                                                 const float* __restrict__ Wk) {
    __shared__ __align__(16) union {
        struct { float Ah[128 * PA]; float Al[128 * PA];
                 float Bh[64 * PA];  float Bl[64 * PA]; } g;
        struct { float Kp[128 * 64]; float Qs[64 * 64]; } e;   // 48 KB
    } sm;

    int tid = threadIdx.x;
    int mBase = blockIdx.x * 128;
    int b = mBase >> 12;
    int sBase = mBase & (NS - 1);
    int h = blockIdx.y;
    int bh = b * NH + h;

    float c[2][4][4] = {};
    gemm_tf32_128x64<true>(key, Wk + (size_t)h * 64 * NC, mBase, c,
                           sm.g.Ah, sm.g.Al, sm.g.Bh, sm.g.Bl, tid);

    __syncthreads();  // all warps done reading GEMM smem before union repurpose

    // Store kp accumulators to smem [s][d]
    {
        int lane = tid & 31;
        int warpM = (tid >> 5) & 3, warpN = tid >> 7;
        int grp = lane >> 2, qd = lane & 3;
#pragma unroll
        for (int mi = 0; mi < 2; ++mi)
#pragma unroll
            for (int nj = 0; nj < 4; ++nj) {
                int row = warpM * 32 + mi * 16 + grp;
                int col = warpN * 32 + nj * 8 + 2 * qd;
                *(float2*)&sm.e.Kp[row * 64 + col] =
                    make_float2(c[mi][nj][0], c[mi][nj][1]);
                *(float2*)&sm.e.Kp[(row + 8) * 64 + col] =
                    make_float2(c[mi][nj][2], c[mi][nj][3]);
            }
    }
    // Load q^T tile [d][n]
    {
        const float* qsrc = g_qT + (size_t)bh * ND * NG;
#pragma unroll
        for (int r = 0; r < 4; ++r) {
            int off = (tid + 256 * r) * 4;
            *(float4*)&sm.e.Qs[off] = *(const float4*)&qsrc[off];
        }
    }
    __syncthreads();

    // scores[128 s][64 n] in fp32, then argmax over n
    int tr = tid >> 4, tc = tid & 15;
    float acc2[8][4] = {};
#pragma unroll 8
    for (int d = 0; d < 64; ++d) {
        float4 q4 = *(const float4*)&sm.e.Qs[d * 64 + tc * 4];
#pragma unroll
        for (int i = 0; i < 8; ++i) {
            float a = sm.e.Kp[(tr * 8 + i) * 64 + d];
            acc2[i][0] += a * q4.x;
            acc2[i][1] += a * q4.y;
            acc2[i][2] += a * q4.z;
            acc2[i][3] += a * q4.w;
        }
    }
#pragma unroll
    for (int i = 0; i < 8; ++i) {
        float mv = acc2[i][0];
        int mi = tc * 4;
#pragma unroll
        for (int j = 1; j < 4; ++j)
            if (acc2[i][j] > mv) { mv = acc2[i][j]; mi = tc * 4 + j; }
#pragma unroll
        for (int off = 8; off >= 1; off >>= 1) {
            float ov = __shfl_down_sync(0xffffffffu, mv, off, 16);
            int   oi = __shfl_down_sync(0xffffffffu, mi, off, 16);
            if (ov > mv || (ov == mv && oi < mi)) { mv = ov; mi = oi; }
        }
        if (tc == 0) {
            g_idx[bh * NS + sBase + tr * 8 + i] = mi;
            atomicAdd(&g_cnt[bh * NG + mi], 1);
        }
    }
}

// ---------------------------------------------------------------------------
// K3: vp = key@Wv^T via 1xTF32 + fused atomic scatter
// ---------------------------------------------------------------------------
__global__ void __launch_bounds__(256) k3_scatter(const float* __restrict__ key,
                                                  const float* __restrict__ Wv) {
    __shared__ __align__(16) struct { float Ah[128 * PA]; float Bh[64 * PA]; } sm;

    int tid = threadIdx.x;
    int mBase = blockIdx.x * 128;
    int b = mBase >> 12;
    int sBase = mBase & (NS - 1);
    int h = blockIdx.y;
    int bh = b * NH + h;

    float c[2][4][4] = {};
    gemm_tf32_128x64<false>(key, Wv + (size_t)h * 64 * NC, mBase, c,
                            sm.Ah, nullptr, sm.Bh, nullptr, tid);

    int lane = tid & 31;
    int warpM = (tid >> 5) & 3, warpN = tid >> 7;
    int grp = lane >> 2, qd = lane & 3;
#pragma unroll
    for (int mi = 0; mi < 2; ++mi) {
        int s0 = sBase + warpM * 32 + mi * 16 + grp;
        int n0 = g_idx[bh * NS + s0];
        int n1 = g_idx[bh * NS + s0 + 8];
#pragma unroll
        for (int nj = 0; nj < 4; ++nj) {
            int d = warpN * 32 + nj * 8 + 2 * qd;
            float* p0 = &g_acc[(bh * NG + n0) * ND + d];
            atomicAdd(p0, c[mi][nj][0]);
            atomicAdd(p0 + 1, c[mi][nj][1]);
            float* p1 = &g_acc[(bh * NG + n1) * ND + d];
            atomicAdd(p1, c[mi][nj][2]);
            atomicAdd(p1 + 1, c[mi][nj][3]);
        }
    }
}

// ---------------------------------------------------------------------------
// K4: normalize + out = tmp @ Wp^T + bp (fp32, tiny)
// ---------------------------------------------------------------------------
__global__ void __launch_bounds__(256) k_finalize(const float* __restrict__ Wp,
                                                  const float* __restrict__ bp,
                                                  float* __restrict__ out) {
    __shared__ float As[BK * AP];
    __shared__ float Bs[BK * BP2];
    int tid = threadIdx.x;
    int trow = tid >> 4, tcol = tid & 15;
    int mBase = blockIdx.x * BM;
    int nBase = blockIdx.y * BN;

    float c[8][4] = {};
    for (int k0 = 0; k0 < NC; k0 += BK) {
#pragma unroll
        for (int l = 0; l < 2; ++l) {
            int lin = tid * 2 + l;
            int m = lin >> 2;
            int kg = (lin & 3) * 4;
            int gm = mBase + m;
            int b = gm >> 6, n = gm & 63;
            int cc = k0 + kg;
            int h = cc >> 6, d = cc & 63;
            int bh = b * NH + h;
            float inv = 1.0f / (float)(g_cnt[bh * NG + n] + 1);
            float4 v = *(const float4*)&g_acc[(bh * NG + n) * ND + d];
            As[(kg + 0) * AP + m] = v.x * inv;
            As[(kg + 1) * AP + m] = v.y * inv;
            As[(kg + 2) * AP + m] = v.z * inv;
            As[(kg + 3) * AP + m] = v.w * inv;
        }
        load_B_tile(Wp, nBase, k0, Bs, tid);
        __syncthreads();
        mma_tile(As, Bs, c, trow, tcol);
        __syncthreads();
    }

    float4 bias = *(const float4*)&bp[nBase + tcol * 4];
#pragma unroll
    for (int i = 0; i < 8; ++i) {
        int m = mBase + trow * 8 + i;
        float4 v = make_float4(c[i][0] + bias.x, c[i][1] + bias.y,
                               c[i][2] + bias.z, c[i][3] + bias.w);
        *(float4*)&out[(size_t)m * NC + nBase + tcol * 4] = v;
    }
}

// ---------------------------------------------------------------------------
extern "C" void kernel_launch(void* const* d_in, const int* in_sizes, int n_in,
                              void* d_out, int out_size) {
    const float* query = (const float*)d_in[0];
    const float* key   = (const float*)d_in[1];
    const float* Wq    = (const float*)d_in[2];
    const float* Wk    = (const float*)d_in[3];
    const float* Wv    = (const float*)d_in[4];
    const float* Wp    = (const float*)d_in[5];
    const float* bp    = (const float*)d_in[6];
    float* out = (float*)d_out;

    k_zero<<<(NB * NH * NG * ND + 255) / 256, 256>>>();
    k_qproj<<<dim3(8, 6), 256>>>(query, Wq);
    k2_assign<<<dim3((NB * NS) / 128, NH), 256>>>(key, Wk);
    k3_scatter<<<dim3((NB * NS) / 128, NH), 256>>>(key, Wv);
    k_finalize<<<dim3(8, 6), 256>>>(Wp, bp, out);
}